// round 7
// baseline (speedup 1.0000x reference)
#include <cuda_runtime.h>

// DCN cross layer, L=3, D=1024, B=16384 — algebraic form, warp-autonomous.
//   a_l  = dot(x, W_l)  (3 independent dots)
//   d_ml = dot(bias_m, W_l)  (batch-independent, once per CTA)
//   alpha recurrence, out = alpha*x + (b0+b1+b2)
// One warp per TWO rows (W smem loads shared across both), NO barriers in the
// row path. vs R5: x is NOT held in registers end-to-end — dot phase consumes
// loads immediately, output phase re-reads x from L1. launch_bounds(256,4)
// caps regs at 64 -> 4 CTAs/SM (occ 2x vs R5's 109-reg / 2-CTA build).

static constexpr int D  = 1024;
static constexpr int F4 = D / 4;            // 256 float4 per row
static constexpr int THREADS = 256;
static constexpr int NWARP = THREADS / 32;  // 8
static constexpr int ROWS_PER_CTA = NWARP * 2;   // 16

__device__ __forceinline__ float dot4(float4 a, float4 b) {
    return fmaf(a.x, b.x, fmaf(a.y, b.y, fmaf(a.z, b.z, a.w * b.w)));
}
__device__ __forceinline__ float wred(float v) {
#pragma unroll
    for (int o = 16; o > 0; o >>= 1)
        v += __shfl_xor_sync(0xffffffffu, v, o);
    return v;
}

__global__ __launch_bounds__(THREADS, 4)
void cross_layer_kernel(const float* __restrict__ x,
                        const float* __restrict__ W,
                        const float* __restrict__ bias,
                        float* __restrict__ out)
{
    __shared__ float4 Ws[3][F4];
    __shared__ float4 Bs[F4];               // b0+b1+b2
    __shared__ float  dred[NWARP][2];

    const int t    = threadIdx.x;
    const int warp = t >> 5;
    const int lane = t & 31;

    // ---- prologue (once per CTA): smem fill + d-constants ----
    const float4* W4 = reinterpret_cast<const float4*>(W);
    const float4* B4 = reinterpret_cast<const float4*>(bias);
    float4 w1 = W4[F4 + t];
    float4 w2 = W4[2 * F4 + t];
    Ws[0][t] = W4[t];
    Ws[1][t] = w1;
    Ws[2][t] = w2;
    float4 b0 = B4[t], b1 = B4[F4 + t], b2 = B4[2 * F4 + t];
    float4 bs;
    bs.x = b0.x + b1.x + b2.x;  bs.y = b0.y + b1.y + b2.y;
    bs.z = b0.z + b1.z + b2.z;  bs.w = b0.w + b1.w + b2.w;
    Bs[t] = bs;

    float p01 = wred(dot4(b0, w1));
    float p2  = wred(dot4(b0, w2) + dot4(b1, w2));     // d02 + d12
    if (lane == 0) { dred[warp][0] = p01; dred[warp][1] = p2; }
    __syncthreads();

    float d01 = 0.f, d2 = 0.f;
#pragma unroll
    for (int w = 0; w < NWARP; w++) { d01 += dred[w][0]; d2 += dred[w][1]; }

    // ---- two rows per warp, fully independent, no barriers ----
    const size_t rowA = (size_t)blockIdx.x * ROWS_PER_CTA + warp * 2;
    const float4* xra = reinterpret_cast<const float4*>(x) + rowA * F4;
    const float4* xrb = xra + F4;
    float4* ora = reinterpret_cast<float4*>(out) + rowA * F4;
    float4* orb = ora + F4;

    // dot phase: consume x loads immediately (no long-lived x registers)
    float a0 = 0.f, a1 = 0.f, a2 = 0.f;
    float c0 = 0.f, c1 = 0.f, c2 = 0.f;
#pragma unroll
    for (int j = 0; j < 8; j++) {
        const int idx = lane + 32 * j;
        float4 xa = __ldg(xra + idx);       // cached: re-read below hits L1
        float4 xb = __ldg(xrb + idx);
        float4 q0 = Ws[0][idx], q1 = Ws[1][idx], q2 = Ws[2][idx];
        a0 = fmaf(xa.x, q0.x, fmaf(xa.y, q0.y, fmaf(xa.z, q0.z, fmaf(xa.w, q0.w, a0))));
        c0 = fmaf(xb.x, q0.x, fmaf(xb.y, q0.y, fmaf(xb.z, q0.z, fmaf(xb.w, q0.w, c0))));
        a1 = fmaf(xa.x, q1.x, fmaf(xa.y, q1.y, fmaf(xa.z, q1.z, fmaf(xa.w, q1.w, a1))));
        c1 = fmaf(xb.x, q1.x, fmaf(xb.y, q1.y, fmaf(xb.z, q1.z, fmaf(xb.w, q1.w, c1))));
        a2 = fmaf(xa.x, q2.x, fmaf(xa.y, q2.y, fmaf(xa.z, q2.z, fmaf(xa.w, q2.w, a2))));
        c2 = fmaf(xb.x, q2.x, fmaf(xb.y, q2.y, fmaf(xb.z, q2.z, fmaf(xb.w, q2.w, c2))));
    }
    a0 = wred(a0); a1 = wred(a1); a2 = wred(a2);
    c0 = wred(c0); c1 = wred(c1); c2 = wred(c2);

    // scalar alpha recurrences
    float ala = 1.f + a0;
    ala += fmaf(ala, a1, d01);
    ala += fmaf(ala, a2, d2);
    float alb = 1.f + c0;
    alb += fmaf(alb, c1, d01);
    alb += fmaf(alb, c2, d2);

    // output: re-read x (L1-hot), fma with shared Bs, streaming store
#pragma unroll
    for (int j = 0; j < 8; j++) {
        const int idx = lane + 32 * j;
        float4 xa = __ldg(xra + idx);
        float4 xb = __ldg(xrb + idx);
        float4 c = Bs[idx];
        float4 oa, ob;
        oa.x = fmaf(ala, xa.x, c.x);  ob.x = fmaf(alb, xb.x, c.x);
        oa.y = fmaf(ala, xa.y, c.y);  ob.y = fmaf(alb, xb.y, c.y);
        oa.z = fmaf(ala, xa.z, c.z);  ob.z = fmaf(alb, xb.z, c.z);
        oa.w = fmaf(ala, xa.w, c.w);  ob.w = fmaf(alb, xb.w, c.w);
        __stcs(ora + idx, oa);
        __stcs(orb + idx, ob);
    }
}

extern "C" void kernel_launch(void* const* d_in, const int* in_sizes, int n_in,
                              void* d_out, int out_size)
{
    const float* x    = (const float*)d_in[0];   // (B, D, 1)
    const float* W    = (const float*)d_in[1];   // (L, D, 1)
    const float* bias = (const float*)d_in[2];   // (L, D, 1)
    float* out = (float*)d_out;

    const int B = in_sizes[0] / D;               // 16384
    cross_layer_kernel<<<B / ROWS_PER_CTA, THREADS>>>(x, W, bias, out);
}

// round 8
// speedup vs baseline: 1.3236x; 1.3236x over previous
#include <cuda_runtime.h>

// DCN cross layer, L=3, D=1024, B=16384 — algebraic form, warp-autonomous.
//   a_l  = dot(x, W_l); d_ml = dot(bias_m, W_l) (per-CTA constants);
//   alpha recurrence; out = alpha*x + (b0+b1+b2).
// One warp per TWO rows (W smem loads shared), NO barriers in the row path.
// vs R5 (21.2us best): x registers are released after the dot phase — the
// output phase re-reads x in a BURST (stays latency-tolerant, unlike R7's
// serialized load-use loop) — freeing ~40 regs so launch_bounds(256,3) gives
// 3 CTAs/SM (24 warps vs R5's 13) while per-warp MLP stays 16.

static constexpr int D  = 1024;
static constexpr int F4 = D / 4;            // 256 float4 per row
static constexpr int THREADS = 256;
static constexpr int NWARP = THREADS / 32;  // 8
static constexpr int ROWS_PER_CTA = NWARP * 2;   // 16

__device__ __forceinline__ float dot4(float4 a, float4 b) {
    return fmaf(a.x, b.x, fmaf(a.y, b.y, fmaf(a.z, b.z, a.w * b.w)));
}
__device__ __forceinline__ float wred(float v) {
#pragma unroll
    for (int o = 16; o > 0; o >>= 1)
        v += __shfl_xor_sync(0xffffffffu, v, o);
    return v;
}

__global__ __launch_bounds__(THREADS, 3)
void cross_layer_kernel(const float* __restrict__ x,
                        const float* __restrict__ W,
                        const float* __restrict__ bias,
                        float* __restrict__ out)
{
    __shared__ float4 Ws[3][F4];
    __shared__ float4 Bs[F4];               // b0+b1+b2
    __shared__ float  dred[NWARP][2];

    const int t    = threadIdx.x;
    const int warp = t >> 5;
    const int lane = t & 31;

    // ---- prologue (once per CTA): smem fill + d-constants ----
    const float4* W4 = reinterpret_cast<const float4*>(W);
    const float4* B4 = reinterpret_cast<const float4*>(bias);
    float4 w1 = W4[F4 + t];
    float4 w2 = W4[2 * F4 + t];
    Ws[0][t] = W4[t];
    Ws[1][t] = w1;
    Ws[2][t] = w2;
    float4 b0 = B4[t], b1 = B4[F4 + t], b2 = B4[2 * F4 + t];
    float4 bs;
    bs.x = b0.x + b1.x + b2.x;  bs.y = b0.y + b1.y + b2.y;
    bs.z = b0.z + b1.z + b2.z;  bs.w = b0.w + b1.w + b2.w;
    Bs[t] = bs;

    float p01 = wred(dot4(b0, w1));
    float p2  = wred(dot4(b0, w2) + dot4(b1, w2));     // d02 + d12
    if (lane == 0) { dred[warp][0] = p01; dred[warp][1] = p2; }
    __syncthreads();

    float d01 = 0.f, d2 = 0.f;
#pragma unroll
    for (int w = 0; w < NWARP; w++) { d01 += dred[w][0]; d2 += dred[w][1]; }

    // ---- two rows per warp, fully independent, no barriers ----
    const size_t rowA = (size_t)blockIdx.x * ROWS_PER_CTA + warp * 2;
    const float4* xra = reinterpret_cast<const float4*>(x) + rowA * F4;
    const float4* xrb = xra + F4;
    float4* ora = reinterpret_cast<float4*>(out) + rowA * F4;
    float4* orb = ora + F4;

    // burst-load both rows (16 independent LDG.128 in flight)
    float4 xa[8], xb[8];
#pragma unroll
    for (int j = 0; j < 8; j++) xa[j] = __ldg(xra + lane + 32 * j);
#pragma unroll
    for (int j = 0; j < 8; j++) xb[j] = __ldg(xrb + lane + 32 * j);

    // dot phase: each W smem load feeds both rows; x dies at the end of this loop
    float a0 = 0.f, a1 = 0.f, a2 = 0.f;
    float c0 = 0.f, c1 = 0.f, c2 = 0.f;
#pragma unroll
    for (int j = 0; j < 8; j++) {
        const int idx = lane + 32 * j;
        float4 q0 = Ws[0][idx], q1 = Ws[1][idx], q2 = Ws[2][idx];
        a0 = fmaf(xa[j].x, q0.x, fmaf(xa[j].y, q0.y, fmaf(xa[j].z, q0.z, fmaf(xa[j].w, q0.w, a0))));
        c0 = fmaf(xb[j].x, q0.x, fmaf(xb[j].y, q0.y, fmaf(xb[j].z, q0.z, fmaf(xb[j].w, q0.w, c0))));
        a1 = fmaf(xa[j].x, q1.x, fmaf(xa[j].y, q1.y, fmaf(xa[j].z, q1.z, fmaf(xa[j].w, q1.w, a1))));
        c1 = fmaf(xb[j].x, q1.x, fmaf(xb[j].y, q1.y, fmaf(xb[j].z, q1.z, fmaf(xb[j].w, q1.w, c1))));
        a2 = fmaf(xa[j].x, q2.x, fmaf(xa[j].y, q2.y, fmaf(xa[j].z, q2.z, fmaf(xa[j].w, q2.w, a2))));
        c2 = fmaf(xb[j].x, q2.x, fmaf(xb[j].y, q2.y, fmaf(xb[j].z, q2.z, fmaf(xb[j].w, q2.w, c2))));
    }
    a0 = wred(a0); a1 = wred(a1); a2 = wred(a2);
    c0 = wred(c0); c1 = wred(c1); c2 = wred(c2);

    // scalar alpha recurrences
    float ala = 1.f + a0;
    ala += fmaf(ala, a1, d01);
    ala += fmaf(ala, a2, d2);
    float alb = 1.f + c0;
    alb += fmaf(alb, c1, d01);
    alb += fmaf(alb, c2, d2);

    // output phase: burst re-read of x (L1/L2 hot), then fma + streaming store.
    float4 ya[4], yb[4];
#pragma unroll
    for (int half = 0; half < 2; half++) {
#pragma unroll
        for (int j = 0; j < 4; j++) ya[j] = __ldg(xra + lane + 32 * (4 * half + j));
#pragma unroll
        for (int j = 0; j < 4; j++) yb[j] = __ldg(xrb + lane + 32 * (4 * half + j));
#pragma unroll
        for (int j = 0; j < 4; j++) {
            const int idx = lane + 32 * (4 * half + j);
            float4 c = Bs[idx];
            float4 oa, ob;
            oa.x = fmaf(ala, ya[j].x, c.x);  ob.x = fmaf(alb, yb[j].x, c.x);
            oa.y = fmaf(ala, ya[j].y, c.y);  ob.y = fmaf(alb, yb[j].y, c.y);
            oa.z = fmaf(ala, ya[j].z, c.z);  ob.z = fmaf(alb, yb[j].z, c.z);
            oa.w = fmaf(ala, ya[j].w, c.w);  ob.w = fmaf(alb, yb[j].w, c.w);
            __stcs(ora + idx, oa);
            __stcs(orb + idx, ob);
        }
    }
}

extern "C" void kernel_launch(void* const* d_in, const int* in_sizes, int n_in,
                              void* d_out, int out_size)
{
    const float* x    = (const float*)d_in[0];   // (B, D, 1)
    const float* W    = (const float*)d_in[1];   // (L, D, 1)
    const float* bias = (const float*)d_in[2];   // (L, D, 1)
    float* out = (float*)d_out;

    const int B = in_sizes[0] / D;               // 16384
    cross_layer_kernel<<<B / ROWS_PER_CTA, THREADS>>>(x, W, bias, out);
}

// round 9
// speedup vs baseline: 1.5768x; 1.1913x over previous
#include <cuda_runtime.h>

// DCN cross layer, L=3, D=1024, B=16384 — algebraic form, persistent+pipelined.
//   a_l = dot(x, W_l); d_ml = dot(bias_m, W_l) (per-CTA constants);
//   alpha recurrence; out = alpha*x + (b0+b1+b2).
// Warp-autonomous (no barriers in row path), 2 rows per warp per step.
// Software pipeline: dots consume x regs -> burst-prefetch NEXT pair into the
// same regs -> wred/alpha/output of current pair (x re-read from L1/L2; that
// latency only feeds STG so it's off the critical path). Persistent grid of
// 304 CTAs (2/SM) with warp-strided pair assignment for perfect balance.

static constexpr int D  = 1024;
static constexpr int F4 = D / 4;            // 256 float4 per row
static constexpr int THREADS = 256;
static constexpr int NWARP = THREADS / 32;  // 8
static constexpr int GRID = 304;            // 2 CTAs/SM x 152 SMs (GB300)
static constexpr int TOTAL_WARPS = GRID * NWARP;   // 2432

__device__ __forceinline__ float dot4(float4 a, float4 b) {
    return fmaf(a.x, b.x, fmaf(a.y, b.y, fmaf(a.z, b.z, a.w * b.w)));
}
__device__ __forceinline__ float wred(float v) {
#pragma unroll
    for (int o = 16; o > 0; o >>= 1)
        v += __shfl_xor_sync(0xffffffffu, v, o);
    return v;
}

__global__ __launch_bounds__(THREADS, 2)
void cross_layer_kernel(const float* __restrict__ x,
                        const float* __restrict__ W,
                        const float* __restrict__ bias,
                        float* __restrict__ out,
                        int total_pairs)
{
    __shared__ float4 Ws[3][F4];
    __shared__ float4 Bs[F4];               // b0+b1+b2
    __shared__ float  dred[NWARP][2];

    const int t    = threadIdx.x;
    const int warp = t >> 5;
    const int lane = t & 31;

    // ---- prologue (once per CTA): smem fill + d-constants ----
    const float4* W4 = reinterpret_cast<const float4*>(W);
    const float4* B4 = reinterpret_cast<const float4*>(bias);
    float4 w1 = W4[F4 + t];
    float4 w2 = W4[2 * F4 + t];
    Ws[0][t] = W4[t];
    Ws[1][t] = w1;
    Ws[2][t] = w2;
    float4 b0 = B4[t], b1 = B4[F4 + t], b2 = B4[2 * F4 + t];
    float4 bs;
    bs.x = b0.x + b1.x + b2.x;  bs.y = b0.y + b1.y + b2.y;
    bs.z = b0.z + b1.z + b2.z;  bs.w = b0.w + b1.w + b2.w;
    Bs[t] = bs;

    float p01 = wred(dot4(b0, w1));
    float p2  = wred(dot4(b0, w2) + dot4(b1, w2));     // d02 + d12
    if (lane == 0) { dred[warp][0] = p01; dred[warp][1] = p2; }
    __syncthreads();

    float d01 = 0.f, d2 = 0.f;
#pragma unroll
    for (int w = 0; w < NWARP; w++) { d01 += dred[w][0]; d2 += dred[w][1]; }

    // ---- persistent, warp-strided pair loop (pair = 2 rows) ----
    const float4* X4 = reinterpret_cast<const float4*>(x);
    float4*       O4 = reinterpret_cast<float4*>(out);

    int p = blockIdx.x * NWARP + warp;

    float4 xa[8], xb[8];
    if (p < total_pairs) {
        const float4* xr = X4 + (size_t)p * 2 * F4;
#pragma unroll
        for (int j = 0; j < 8; j++) xa[j] = __ldg(xr + lane + 32 * j);
#pragma unroll
        for (int j = 0; j < 8; j++) xb[j] = __ldg(xr + F4 + lane + 32 * j);
    }

    while (p < total_pairs) {
        const int pn = p + TOTAL_WARPS;

        // dot phase: each W smem load feeds both rows; x regs die here
        float a0 = 0.f, a1 = 0.f, a2 = 0.f;
        float c0 = 0.f, c1 = 0.f, c2 = 0.f;
#pragma unroll
        for (int j = 0; j < 8; j++) {
            const int idx = lane + 32 * j;
            float4 q0 = Ws[0][idx], q1 = Ws[1][idx], q2 = Ws[2][idx];
            a0 = fmaf(xa[j].x, q0.x, fmaf(xa[j].y, q0.y, fmaf(xa[j].z, q0.z, fmaf(xa[j].w, q0.w, a0))));
            c0 = fmaf(xb[j].x, q0.x, fmaf(xb[j].y, q0.y, fmaf(xb[j].z, q0.z, fmaf(xb[j].w, q0.w, c0))));
            a1 = fmaf(xa[j].x, q1.x, fmaf(xa[j].y, q1.y, fmaf(xa[j].z, q1.z, fmaf(xa[j].w, q1.w, a1))));
            c1 = fmaf(xb[j].x, q1.x, fmaf(xb[j].y, q1.y, fmaf(xb[j].z, q1.z, fmaf(xb[j].w, q1.w, c1))));
            a2 = fmaf(xa[j].x, q2.x, fmaf(xa[j].y, q2.y, fmaf(xa[j].z, q2.z, fmaf(xa[j].w, q2.w, a2))));
            c2 = fmaf(xb[j].x, q2.x, fmaf(xb[j].y, q2.y, fmaf(xb[j].z, q2.z, fmaf(xb[j].w, q2.w, c2))));
        }

        // prefetch NEXT pair into the freed x regs (hides DRAM under wred/output)
        if (pn < total_pairs) {
            const float4* xr2 = X4 + (size_t)pn * 2 * F4;
#pragma unroll
            for (int j = 0; j < 8; j++) xa[j] = __ldg(xr2 + lane + 32 * j);
#pragma unroll
            for (int j = 0; j < 8; j++) xb[j] = __ldg(xr2 + F4 + lane + 32 * j);
        }

        a0 = wred(a0); a1 = wred(a1); a2 = wred(a2);
        c0 = wred(c0); c1 = wred(c1); c2 = wred(c2);

        float ala = 1.f + a0;
        ala += fmaf(ala, a1, d01);
        ala += fmaf(ala, a2, d2);
        float alb = 1.f + c0;
        alb += fmaf(alb, c1, d01);
        alb += fmaf(alb, c2, d2);

        // output: burst re-read current pair's x (L1/L2 hot) -> fma -> stream store
        {
            const float4* xr = X4 + (size_t)p * 2 * F4;
            float4*       orp = O4 + (size_t)p * 2 * F4;
#pragma unroll
            for (int j = 0; j < 8; j++) {
                const int idx = lane + 32 * j;
                float4 fa = __ldg(xr + idx);
                float4 fb = __ldg(xr + F4 + idx);
                float4 c  = Bs[idx];
                float4 oa, ob;
                oa.x = fmaf(ala, fa.x, c.x);  ob.x = fmaf(alb, fb.x, c.x);
                oa.y = fmaf(ala, fa.y, c.y);  ob.y = fmaf(alb, fb.y, c.y);
                oa.z = fmaf(ala, fa.z, c.z);  ob.z = fmaf(alb, fb.z, c.z);
                oa.w = fmaf(ala, fa.w, c.w);  ob.w = fmaf(alb, fb.w, c.w);
                __stcs(orp + idx, oa);
                __stcs(orp + F4 + idx, ob);
            }
        }
        p = pn;
    }
}

extern "C" void kernel_launch(void* const* d_in, const int* in_sizes, int n_in,
                              void* d_out, int out_size)
{
    const float* x    = (const float*)d_in[0];   // (B, D, 1)
    const float* W    = (const float*)d_in[1];   // (L, D, 1)
    const float* bias = (const float*)d_in[2];   // (L, D, 1)
    float* out = (float*)d_out;

    const int B = in_sizes[0] / D;               // 16384
    cross_layer_kernel<<<GRID, THREADS>>>(x, W, bias, out, B / 2);
}